// round 1
// baseline (speedup 1.0000x reference)
#include <cuda_runtime.h>
#include <math.h>

#define BATCH 16384
#define IN_CH 4096
#define COMP  512

// Scratch (allocation-free rule: __device__ globals)
__device__ float g_h[(size_t)BATCH * IN_CH];   // 256 MB activation buffer (reused)
__device__ float g_z[(size_t)BATCH * COMP];    // 32 MB latent buffer

// ---------------- JAX Threefry-2x32 noise (partitionable scheme) ----------------
// key = jax.random.key(42) -> (k_hi, k_lo) = (0, 42)
// partitionable 32-bit bits for flat index i: out0 ^ out1 of threefry2x32(key, (0, i))

__device__ __forceinline__ unsigned rotl32(unsigned v, int r) {
    return (v << r) | (v >> (32 - r));
}

__device__ __forceinline__ unsigned threefry2x32_xor(unsigned c_hi, unsigned c_lo) {
    const unsigned k1 = 0u;
    const unsigned k2 = 42u;
    const unsigned k3 = 0x1BD11BDAu ^ k1 ^ k2;
    unsigned x0 = c_hi + k1;
    unsigned x1 = c_lo + k2;
#define TFR(r) { x0 += x1; x1 = rotl32(x1, (r)); x1 ^= x0; }
    TFR(13) TFR(15) TFR(26) TFR(6)
    x0 += k2; x1 += k3 + 1u;
    TFR(17) TFR(29) TFR(16) TFR(24)
    x0 += k3; x1 += k1 + 2u;
    TFR(13) TFR(15) TFR(26) TFR(6)
    x0 += k1; x1 += k2 + 3u;
    TFR(17) TFR(29) TFR(16) TFR(24)
    x0 += k2; x1 += k3 + 4u;
    TFR(13) TFR(15) TFR(26) TFR(6)
    x0 += k3; x1 += k1 + 5u;
#undef TFR
    return x0 ^ x1;
}

__device__ __forceinline__ float jax_awgn_noise(unsigned idx) {
    unsigned bits = threefry2x32_xor(0u, idx);
    // uniform in [0,1): (bits >> 9) | 0x3F800000 gives [1,2), minus 1
    float f = __uint_as_float((bits >> 9) | 0x3F800000u) - 1.0f;
    // jax: lo = nextafter(-1,0) = -0.99999994f, hi = 1.0; (hi-lo) rounds to 2.0f in f32
    const float lo = -0.99999994f;
    float u = fmaf(f, 2.0f, lo);
    u = fmaxf(lo, u);
    // normal = sqrt(2) * erfinv(u), then * NOISE_SCALE = 1/sqrt(2*R*SNR), R=2, SNR=5.01187
    float n = 1.41421356f * erfinvf(u);
    const float NOISE_SCALE = 0.223341852f;  // f32(1/sqrt(20.04748))
    return n * NOISE_SCALE;
}

// ---------------- fused fp32 GEMM: C = epilogue(A @ B + bias) ----------------
// A [M,K] row-major, B [K,N] row-major. Tiles: 128x128xK8, 256 threads, 8x8/thread.

enum { EP_RELU = 0, EP_CLAMP_NOISE = 1, EP_PLAIN = 2 };

template <int MODE>
__global__ __launch_bounds__(256, 2)
void sgemm_ep(const float* __restrict__ A, const float* __restrict__ B,
              const float* __restrict__ bias, float* __restrict__ C,
              int M, int N, int K)
{
    __shared__ float As[8][128];   // A^T tile
    __shared__ float Bs[8][128];

    const int tid = threadIdx.x;
    const int tx = tid & 15;       // 16 threads along N
    const int ty = tid >> 4;       // 16 threads along M

    const float* Ab = A + (size_t)blockIdx.y * 128 * K;
    const float* Bb = B + blockIdx.x * 128;

    const int a_row = tid >> 1;            // 0..127
    const int a_col = (tid & 1) << 2;      // 0 or 4
    const int b_row = tid >> 5;            // 0..7
    const int b_col = (tid & 31) << 2;     // 0..124

    float acc[8][8];
#pragma unroll
    for (int i = 0; i < 8; i++)
#pragma unroll
        for (int j = 0; j < 8; j++) acc[i][j] = 0.0f;

    for (int k0 = 0; k0 < K; k0 += 8) {
        float4 av = *(const float4*)(Ab + (size_t)a_row * K + k0 + a_col);
        float4 bv = *(const float4*)(Bb + (size_t)(k0 + b_row) * N + b_col);
        As[a_col + 0][a_row] = av.x;
        As[a_col + 1][a_row] = av.y;
        As[a_col + 2][a_row] = av.z;
        As[a_col + 3][a_row] = av.w;
        *(float4*)&Bs[b_row][b_col] = bv;
        __syncthreads();

#pragma unroll
        for (int k = 0; k < 8; k++) {
            float ra[8], rb[8];
            *(float4*)&ra[0] = *(const float4*)&As[k][ty * 8 + 0];
            *(float4*)&ra[4] = *(const float4*)&As[k][ty * 8 + 4];
            *(float4*)&rb[0] = *(const float4*)&Bs[k][tx * 8 + 0];
            *(float4*)&rb[4] = *(const float4*)&Bs[k][tx * 8 + 4];
#pragma unroll
            for (int i = 0; i < 8; i++)
#pragma unroll
                for (int j = 0; j < 8; j++)
                    acc[i][j] = fmaf(ra[i], rb[j], acc[i][j]);
        }
        __syncthreads();
    }

    const int row0 = blockIdx.y * 128 + ty * 8;
    const int col0 = blockIdx.x * 128 + tx * 8;
    float bsv[8];
#pragma unroll
    for (int j = 0; j < 8; j++) bsv[j] = bias[col0 + j];

#pragma unroll
    for (int i = 0; i < 8; i++) {
        const size_t base = (size_t)(row0 + i) * N + col0;
#pragma unroll
        for (int j = 0; j < 8; j++) {
            float c = acc[i][j] + bsv[j];
            if (MODE == EP_RELU) {
                c = fmaxf(c, 0.0f);
            } else if (MODE == EP_CLAMP_NOISE) {
                c = fminf(fmaxf(c, 0.0f), 1.0f);           // QP box projection == clamp
                c += jax_awgn_noise((unsigned)(base + j)); // flat idx into [B, COMP]
            }
            C[base + j] = c;
        }
    }
}

// ---------------- launch ----------------
extern "C" void kernel_launch(void* const* d_in, const int* in_sizes, int n_in,
                              void* d_out, int out_size)
{
    (void)in_sizes; (void)n_in; (void)out_size;
    const float* x   = (const float*)d_in[0];
    const float* ew1 = (const float*)d_in[1];
    const float* eb1 = (const float*)d_in[2];
    const float* ew2 = (const float*)d_in[3];
    const float* eb2 = (const float*)d_in[4];
    const float* dw1 = (const float*)d_in[5];
    const float* db1 = (const float*)d_in[6];
    const float* dw2 = (const float*)d_in[7];
    const float* db2 = (const float*)d_in[8];
    float* out = (float*)d_out;

    float* h = nullptr;
    float* z = nullptr;
    cudaGetSymbolAddress((void**)&h, g_h);
    cudaGetSymbolAddress((void**)&z, g_z);

    dim3 blk(256);
    // h = relu(x @ enc_w1 + enc_b1)            [16384, 4096]
    sgemm_ep<EP_RELU><<<dim3(IN_CH / 128, BATCH / 128), blk>>>(x, ew1, eb1, h, BATCH, IN_CH, IN_CH);
    // z = clamp(h @ enc_w2 + enc_b2, 0, 1) + awgn   [16384, 512]
    sgemm_ep<EP_CLAMP_NOISE><<<dim3(COMP / 128, BATCH / 128), blk>>>(h, ew2, eb2, z, BATCH, COMP, IN_CH);
    // h2 = relu(z @ dec_w1 + dec_b1)           [16384, 4096]  (reuse g_h)
    sgemm_ep<EP_RELU><<<dim3(IN_CH / 128, BATCH / 128), blk>>>(z, dw1, db1, h, BATCH, IN_CH, COMP);
    // out = h2 @ dec_w2 + dec_b2               [16384, 4096]
    sgemm_ep<EP_PLAIN><<<dim3(IN_CH / 128, BATCH / 128), blk>>>(h, dw2, db2, out, BATCH, IN_CH, IN_CH);
}

// round 5
// speedup vs baseline: 3.8720x; 3.8720x over previous
#include <cuda_runtime.h>
#include <math.h>
#include <stdint.h>

#define BATCH 16384
#define IN_CH 4096
#define COMP  512

// ---------------- scratch (__device__ globals; no allocation allowed) ----------------
__device__ float g_x [(size_t)BATCH * IN_CH];   // tf32-rounded x
__device__ float g_h [(size_t)BATCH * IN_CH];   // activations (reused)
__device__ float g_z [(size_t)BATCH * COMP];
__device__ float g_wt1[(size_t)IN_CH * IN_CH];  // enc_w1^T  [N,K]
__device__ float g_wt2[(size_t)COMP  * IN_CH];  // enc_w2^T
__device__ float g_wt3[(size_t)IN_CH * COMP];   // dec_w1^T
__device__ float g_wt4[(size_t)IN_CH * IN_CH];  // dec_w2^T

// ---------------- helpers ----------------
__device__ __forceinline__ uint32_t smem_u32(const void* p) {
    uint32_t a;
    asm("{ .reg .u64 t; cvta.to.shared.u64 t, %1; cvt.u32.u64 %0, t; }" : "=r"(a) : "l"(p));
    return a;
}
__device__ __forceinline__ float rna_tf32(float x) {
    uint32_t o; asm("cvt.rna.tf32.f32 %0, %1;" : "=r"(o) : "f"(x));
    return __uint_as_float(o);
}

#define CP_ASYNC16(saddr, gaddr) \
    asm volatile("cp.async.cg.shared.global [%0], [%1], 16;" :: "r"(saddr), "l"(gaddr) : "memory")
#define CP_COMMIT() asm volatile("cp.async.commit_group;" ::: "memory")
#define CP_WAIT(n)  asm volatile("cp.async.wait_group %0;" :: "n"(n) : "memory")

__device__ __forceinline__ void mma_tf32(float* d, uint32_t a0, uint32_t a1, uint32_t a2, uint32_t a3,
                                         uint32_t b0, uint32_t b1) {
    asm volatile("mma.sync.aligned.m16n8k8.row.col.f32.tf32.tf32.f32 "
                 "{%0,%1,%2,%3}, {%4,%5,%6,%7}, {%8,%9}, {%0,%1,%2,%3};"
                 : "+f"(d[0]), "+f"(d[1]), "+f"(d[2]), "+f"(d[3])
                 : "r"(a0), "r"(a1), "r"(a2), "r"(a3), "r"(b0), "r"(b1));
}

// ---------------- JAX Threefry noise (verified bit-exact in round 0) ----------------
__device__ __forceinline__ unsigned rotl32(unsigned v, int r) { return (v << r) | (v >> (32 - r)); }
__device__ __forceinline__ unsigned threefry2x32_xor(unsigned c_hi, unsigned c_lo) {
    const unsigned k1 = 0u, k2 = 42u, k3 = 0x1BD11BDAu ^ k1 ^ k2;
    unsigned x0 = c_hi + k1, x1 = c_lo + k2;
#define TFR(r) { x0 += x1; x1 = rotl32(x1, (r)); x1 ^= x0; }
    TFR(13) TFR(15) TFR(26) TFR(6)
    x0 += k2; x1 += k3 + 1u;
    TFR(17) TFR(29) TFR(16) TFR(24)
    x0 += k3; x1 += k1 + 2u;
    TFR(13) TFR(15) TFR(26) TFR(6)
    x0 += k1; x1 += k2 + 3u;
    TFR(17) TFR(29) TFR(16) TFR(24)
    x0 += k2; x1 += k3 + 4u;
    TFR(13) TFR(15) TFR(26) TFR(6)
    x0 += k3; x1 += k1 + 5u;
#undef TFR
    return x0 ^ x1;
}
__device__ __forceinline__ float jax_awgn_noise(unsigned idx) {
    unsigned bits = threefry2x32_xor(0u, idx);
    float f = __uint_as_float((bits >> 9) | 0x3F800000u) - 1.0f;
    const float lo = -0.99999994f;
    float u = fmaxf(lo, fmaf(f, 2.0f, lo));
    return 1.41421356f * erfinvf(u) * 0.223341852f;
}

// ---------------- prep kernels ----------------
__global__ void round_tf32_kernel(const float4* __restrict__ in, float4* __restrict__ out, int n4) {
    for (int i = blockIdx.x * blockDim.x + threadIdx.x; i < n4; i += gridDim.x * blockDim.x) {
        float4 v = in[i];
        v.x = rna_tf32(v.x); v.y = rna_tf32(v.y); v.z = rna_tf32(v.z); v.w = rna_tf32(v.w);
        out[i] = v;
    }
}
// out[c][r] = rna(in[r][c]); in is [R, C]
__global__ void transpose_rna_kernel(const float* __restrict__ in, float* __restrict__ out, int R, int C) {
    __shared__ float t[32][33];
    int c0 = blockIdx.x * 32, r0 = blockIdx.y * 32;
    int x = threadIdx.x, y = threadIdx.y;
    for (int i = y; i < 32; i += 8) t[i][x] = in[(size_t)(r0 + i) * C + c0 + x];
    __syncthreads();
    for (int i = y; i < 32; i += 8) out[(size_t)(c0 + i) * R + r0 + x] = rna_tf32(t[x][i]);
}

// ---------------- tf32 mma.sync GEMM ----------------
// C[M,N] = ep(A[M,K] @ B^T + bias), B stored [N,K]. CTA tile 128x128x32.
// 8 warps as 4(M) x 2(N): warp tile 32x64 = 2 x 8 m16n8k8 tiles per k-step.

#define BM 128
#define BN 128
#define BK 32
#define NSTAGE 3
#define LDT 36                         // padded row stride (floats) -> conflict-free LDS
#define TILE_F (128 * LDT)             // 4608 floats per operand tile
#define STAGE_F (2 * TILE_F)           // A + B
#define SMEM_BYTES (NSTAGE * STAGE_F * 4)   // 110592

enum { EP_RELU = 0, EP_CLAMP_NOISE = 1, EP_PLAIN = 2 };

// load a 128x32 fp32 tile (row stride ldg) into padded smem tile
__device__ __forceinline__ void load_tile(float* sdst, const float* gsrc, int ldg, int tid) {
#pragma unroll
    for (int i = 0; i < 4; i++) {
        int idx = tid + i * 256;           // 0..1023
        int row = idx >> 3;
        int q   = idx & 7;                 // float4 within 32-float row
        uint32_t sa = smem_u32(sdst + row * LDT + q * 4);
        const float* ga = gsrc + (size_t)row * ldg + q * 4;
        CP_ASYNC16(sa, ga);
    }
}

template <int MODE>
__global__ __launch_bounds__(256, 2)
void gemm_mma(const float* __restrict__ A, const float* __restrict__ B,
              const float* __restrict__ bias, float* __restrict__ C,
              int M, int N, int K)
{
    extern __shared__ float sm[];
    const int tid = threadIdx.x;
    const int wid = tid >> 5;
    const int lane = tid & 31;
    const int g = lane >> 2;              // groupID 0..7
    const int tig = lane & 3;             // thread-in-group 0..3

    const int n0 = blockIdx.x * BN;
    const int m0 = blockIdx.y * BM;
    const int warp_m = (wid >> 1) * 32;   // 0,32,64,96
    const int warp_n = (wid & 1) * 64;    // 0,64
    const int nchunk = K >> 5;

    const float* Ab = A + (size_t)m0 * K;
    const float* Bb = B + (size_t)n0 * K;

    float acc[2][8][4];
#pragma unroll
    for (int mt = 0; mt < 2; mt++)
#pragma unroll
        for (int nt = 0; nt < 8; nt++)
#pragma unroll
            for (int q = 0; q < 4; q++) acc[mt][nt][q] = 0.0f;

    // prologue: issue stages 0,1
#pragma unroll
    for (int s = 0; s < 2; s++) {
        float* st = sm + s * STAGE_F;
        load_tile(st, Ab + s * BK, K, tid);
        load_tile(st + TILE_F, Bb + s * BK, K, tid);
        CP_COMMIT();
    }

    for (int c = 0; c < nchunk; c++) {
        CP_WAIT(1);
        __syncthreads();

        // issue chunk c+2 into buffer (c+2)%3 (freed by the barrier above)
        if (c + 2 < nchunk) {
            int s = (c + 2) % NSTAGE;
            float* st = sm + s * STAGE_F;
            load_tile(st, Ab + (c + 2) * BK, K, tid);
            load_tile(st + TILE_F, Bb + (c + 2) * BK, K, tid);
            CP_COMMIT();
        }

        const float* As = sm + (c % NSTAGE) * STAGE_F;
        const float* Bs = As + TILE_F;

#pragma unroll
        for (int ks = 0; ks < 4; ks++) {
            const int k = ks * 8;
            uint32_t af[2][4], bf[8][2];
#pragma unroll
            for (int mt = 0; mt < 2; mt++) {
                const int r0 = warp_m + mt * 16 + g;
                af[mt][0] = __float_as_uint(As[r0 * LDT + k + tig]);
                af[mt][1] = __float_as_uint(As[(r0 + 8) * LDT + k + tig]);
                af[mt][2] = __float_as_uint(As[r0 * LDT + k + tig + 4]);
                af[mt][3] = __float_as_uint(As[(r0 + 8) * LDT + k + tig + 4]);
            }
#pragma unroll
            for (int nt = 0; nt < 8; nt++) {
                const int n = warp_n + nt * 8 + g;
                bf[nt][0] = __float_as_uint(Bs[n * LDT + k + tig]);
                bf[nt][1] = __float_as_uint(Bs[n * LDT + k + tig + 4]);
            }
#pragma unroll
            for (int mt = 0; mt < 2; mt++)
#pragma unroll
                for (int nt = 0; nt < 8; nt++)
                    mma_tf32(acc[mt][nt], af[mt][0], af[mt][1], af[mt][2], af[mt][3],
                             bf[nt][0], bf[nt][1]);
        }
    }
    CP_WAIT(0);

    // ---- epilogue ----
#pragma unroll
    for (int mt = 0; mt < 2; mt++) {
        const int row_a = m0 + warp_m + mt * 16 + g;
        const int row_b = row_a + 8;
#pragma unroll
        for (int nt = 0; nt < 8; nt++) {
            const int col = n0 + warp_n + nt * 8 + tig * 2;
            const float b0 = bias[col], b1 = bias[col + 1];
            float v0 = acc[mt][nt][0] + b0;
            float v1 = acc[mt][nt][1] + b1;
            float v2 = acc[mt][nt][2] + b0;
            float v3 = acc[mt][nt][3] + b1;
            if (MODE == EP_RELU) {
                v0 = rna_tf32(fmaxf(v0, 0.0f)); v1 = rna_tf32(fmaxf(v1, 0.0f));
                v2 = rna_tf32(fmaxf(v2, 0.0f)); v3 = rna_tf32(fmaxf(v3, 0.0f));
            } else if (MODE == EP_CLAMP_NOISE) {
                v0 = fminf(fmaxf(v0, 0.0f), 1.0f) + jax_awgn_noise((unsigned)((size_t)row_a * N + col));
                v1 = fminf(fmaxf(v1, 0.0f), 1.0f) + jax_awgn_noise((unsigned)((size_t)row_a * N + col + 1));
                v2 = fminf(fmaxf(v2, 0.0f), 1.0f) + jax_awgn_noise((unsigned)((size_t)row_b * N + col));
                v3 = fminf(fmaxf(v3, 0.0f), 1.0f) + jax_awgn_noise((unsigned)((size_t)row_b * N + col + 1));
                v0 = rna_tf32(v0); v1 = rna_tf32(v1); v2 = rna_tf32(v2); v3 = rna_tf32(v3);
            }
            *(float2*)(C + (size_t)row_a * N + col) = make_float2(v0, v1);
            *(float2*)(C + (size_t)row_b * N + col) = make_float2(v2, v3);
        }
    }
}

// ---------------- host launch ----------------
extern "C" void kernel_launch(void* const* d_in, const int* in_sizes, int n_in,
                              void* d_out, int out_size)
{
    (void)in_sizes; (void)n_in; (void)out_size;
    const float* x   = (const float*)d_in[0];
    const float* ew1 = (const float*)d_in[1];
    const float* eb1 = (const float*)d_in[2];
    const float* ew2 = (const float*)d_in[3];
    const float* eb2 = (const float*)d_in[4];
    const float* dw1 = (const float*)d_in[5];
    const float* db1 = (const float*)d_in[6];
    const float* dw2 = (const float*)d_in[7];
    const float* db2 = (const float*)d_in[8];
    float* out = (float*)d_out;

    float *px, *ph, *pz, *w1, *w2, *w3, *w4;
    cudaGetSymbolAddress((void**)&px, g_x);
    cudaGetSymbolAddress((void**)&ph, g_h);
    cudaGetSymbolAddress((void**)&pz, g_z);
    cudaGetSymbolAddress((void**)&w1, g_wt1);
    cudaGetSymbolAddress((void**)&w2, g_wt2);
    cudaGetSymbolAddress((void**)&w3, g_wt3);
    cudaGetSymbolAddress((void**)&w4, g_wt4);

    // prep: tf32-round x; transpose+round the 4 weights into [N,K] layout
    round_tf32_kernel<<<2048, 256>>>((const float4*)x, (float4*)px, (BATCH * IN_CH) / 4);
    dim3 tb(32, 8);
    transpose_rna_kernel<<<dim3(IN_CH / 32, IN_CH / 32), tb>>>(ew1, w1, IN_CH, IN_CH);
    transpose_rna_kernel<<<dim3(COMP  / 32, IN_CH / 32), tb>>>(ew2, w2, IN_CH, COMP);
    transpose_rna_kernel<<<dim3(IN_CH / 32, COMP  / 32), tb>>>(dw1, w3, COMP, IN_CH);
    transpose_rna_kernel<<<dim3(IN_CH / 32, IN_CH / 32), tb>>>(dw2, w4, IN_CH, IN_CH);

    cudaFuncSetAttribute(gemm_mma<EP_RELU>,        cudaFuncAttributeMaxDynamicSharedMemorySize, SMEM_BYTES);
    cudaFuncSetAttribute(gemm_mma<EP_CLAMP_NOISE>, cudaFuncAttributeMaxDynamicSharedMemorySize, SMEM_BYTES);
    cudaFuncSetAttribute(gemm_mma<EP_PLAIN>,       cudaFuncAttributeMaxDynamicSharedMemorySize, SMEM_BYTES);

    // G1: h = relu(x @ enc_w1 + b)            [16384, 4096], K=4096
    gemm_mma<EP_RELU><<<dim3(IN_CH / BN, BATCH / BM), 256, SMEM_BYTES>>>(px, w1, eb1, ph, BATCH, IN_CH, IN_CH);
    // G2: z = clamp(h @ enc_w2 + b) + awgn    [16384, 512],  K=4096
    gemm_mma<EP_CLAMP_NOISE><<<dim3(COMP / BN, BATCH / BM), 256, SMEM_BYTES>>>(ph, w2, eb2, pz, BATCH, COMP, IN_CH);
    // G3: h = relu(z @ dec_w1 + b)            [16384, 4096], K=512
    gemm_mma<EP_RELU><<<dim3(IN_CH / BN, BATCH / BM), 256, SMEM_BYTES>>>(pz, w3, db1, ph, BATCH, IN_CH, COMP);
    // G4: out = h @ dec_w2 + b                [16384, 4096], K=4096
    gemm_mma<EP_PLAIN><<<dim3(IN_CH / BN, BATCH / BM), 256, SMEM_BYTES>>>(ph, w4, db2, out, BATCH, IN_CH, IN_CH);
}

// round 6
// speedup vs baseline: 4.2769x; 1.1046x over previous
#include <cuda_runtime.h>
#include <math.h>
#include <stdint.h>

#define BATCH 16384
#define IN_CH 4096
#define COMP  512

// ---------------- scratch (__device__ globals; no allocation allowed) ----------------
__device__ float g_x [(size_t)BATCH * IN_CH];   // tf32-rounded x
__device__ float g_h [(size_t)BATCH * IN_CH];   // activations (reused)
__device__ float g_z [(size_t)BATCH * COMP];
__device__ float g_wt1[(size_t)IN_CH * IN_CH];  // enc_w1^T  [N,K]
__device__ float g_wt2[(size_t)COMP  * IN_CH];  // enc_w2^T
__device__ float g_wt3[(size_t)IN_CH * COMP];   // dec_w1^T
__device__ float g_wt4[(size_t)IN_CH * IN_CH];  // dec_w2^T

// ---------------- helpers ----------------
__device__ __forceinline__ uint32_t smem_u32(const void* p) {
    uint32_t a;
    asm("{ .reg .u64 t; cvta.to.shared.u64 t, %1; cvt.u32.u64 %0, t; }" : "=r"(a) : "l"(p));
    return a;
}
__device__ __forceinline__ float rna_tf32(float x) {
    uint32_t o; asm("cvt.rna.tf32.f32 %0, %1;" : "=r"(o) : "f"(x));
    return __uint_as_float(o);
}

#define CP_ASYNC16(saddr, gaddr) \
    asm volatile("cp.async.cg.shared.global [%0], [%1], 16;" :: "r"(saddr), "l"(gaddr) : "memory")
#define CP_COMMIT() asm volatile("cp.async.commit_group;" ::: "memory")
#define CP_WAIT(n)  asm volatile("cp.async.wait_group %0;" :: "n"(n) : "memory")

__device__ __forceinline__ void ldsm4(uint32_t* r, uint32_t addr) {
    asm volatile("ldmatrix.sync.aligned.m8n8.x4.shared.b16 {%0,%1,%2,%3}, [%4];"
                 : "=r"(r[0]), "=r"(r[1]), "=r"(r[2]), "=r"(r[3]) : "r"(addr));
}

__device__ __forceinline__ void mma_tf32(float* d, uint32_t a0, uint32_t a1, uint32_t a2, uint32_t a3,
                                         uint32_t b0, uint32_t b1) {
    asm volatile("mma.sync.aligned.m16n8k8.row.col.f32.tf32.tf32.f32 "
                 "{%0,%1,%2,%3}, {%4,%5,%6,%7}, {%8,%9}, {%0,%1,%2,%3};"
                 : "+f"(d[0]), "+f"(d[1]), "+f"(d[2]), "+f"(d[3])
                 : "r"(a0), "r"(a1), "r"(a2), "r"(a3), "r"(b0), "r"(b1));
}

// ---------------- JAX Threefry noise (verified bit-exact in round 0) ----------------
__device__ __forceinline__ unsigned rotl32(unsigned v, int r) { return (v << r) | (v >> (32 - r)); }
__device__ __forceinline__ unsigned threefry2x32_xor(unsigned c_hi, unsigned c_lo) {
    const unsigned k1 = 0u, k2 = 42u, k3 = 0x1BD11BDAu ^ k1 ^ k2;
    unsigned x0 = c_hi + k1, x1 = c_lo + k2;
#define TFR(r) { x0 += x1; x1 = rotl32(x1, (r)); x1 ^= x0; }
    TFR(13) TFR(15) TFR(26) TFR(6)
    x0 += k2; x1 += k3 + 1u;
    TFR(17) TFR(29) TFR(16) TFR(24)
    x0 += k3; x1 += k1 + 2u;
    TFR(13) TFR(15) TFR(26) TFR(6)
    x0 += k1; x1 += k2 + 3u;
    TFR(17) TFR(29) TFR(16) TFR(24)
    x0 += k2; x1 += k3 + 4u;
    TFR(13) TFR(15) TFR(26) TFR(6)
    x0 += k3; x1 += k1 + 5u;
#undef TFR
    return x0 ^ x1;
}
__device__ __forceinline__ float jax_awgn_noise(unsigned idx) {
    unsigned bits = threefry2x32_xor(0u, idx);
    float f = __uint_as_float((bits >> 9) | 0x3F800000u) - 1.0f;
    const float lo = -0.99999994f;
    float u = fmaxf(lo, fmaf(f, 2.0f, lo));
    return 1.41421356f * erfinvf(u) * 0.223341852f;
}

// ---------------- prep kernels ----------------
__global__ void round_tf32_kernel(const float4* __restrict__ in, float4* __restrict__ out, int n4) {
    for (int i = blockIdx.x * blockDim.x + threadIdx.x; i < n4; i += gridDim.x * blockDim.x) {
        float4 v = in[i];
        v.x = rna_tf32(v.x); v.y = rna_tf32(v.y); v.z = rna_tf32(v.z); v.w = rna_tf32(v.w);
        out[i] = v;
    }
}
// out[c][r] = rna(in[r][c]); in is [R, C]
__global__ void transpose_rna_kernel(const float* __restrict__ in, float* __restrict__ out, int R, int C) {
    __shared__ float t[32][33];
    int c0 = blockIdx.x * 32, r0 = blockIdx.y * 32;
    int x = threadIdx.x, y = threadIdx.y;
    for (int i = y; i < 32; i += 8) t[i][x] = in[(size_t)(r0 + i) * C + c0 + x];
    __syncthreads();
    for (int i = y; i < 32; i += 8) out[(size_t)(c0 + i) * R + r0 + x] = rna_tf32(t[x][i]);
}

// ---------------- tf32 mma.sync GEMM (ldmatrix fragments) ----------------
// C[M,N] = ep(A[M,K] @ B^T + bias), B stored [N,K]. CTA tile 128x128x32.
// 8 warps as 4(M) x 2(N): warp tile 32x64 = 2 x 8 m16n8k8 tiles per k-step.

#define BM 128
#define BN 128
#define BK 32
#define NSTAGE 3
#define LDT 36                         // padded row stride (floats) -> conflict-free LDS/LDSM
#define TILE_F (128 * LDT)             // 4608 floats per operand tile
#define STAGE_F (2 * TILE_F)           // A + B
#define SMEM_BYTES (NSTAGE * STAGE_F * 4)   // 110592

enum { EP_RELU = 0, EP_CLAMP_NOISE = 1, EP_PLAIN = 2 };

// load a 128x32 fp32 tile (row stride ldg) into padded smem tile
__device__ __forceinline__ void load_tile(float* sdst, const float* gsrc, int ldg, int tid) {
#pragma unroll
    for (int i = 0; i < 4; i++) {
        int idx = tid + i * 256;           // 0..1023
        int row = idx >> 3;
        int q   = idx & 7;                 // float4 within 32-float row
        uint32_t sa = smem_u32(sdst + row * LDT + q * 4);
        const float* ga = gsrc + (size_t)row * ldg + q * 4;
        CP_ASYNC16(sa, ga);
    }
}

template <int MODE>
__global__ __launch_bounds__(256, 2)
void gemm_mma(const float* __restrict__ A, const float* __restrict__ B,
              const float* __restrict__ bias, float* __restrict__ C,
              int M, int N, int K)
{
    extern __shared__ float sm[];
    const int tid = threadIdx.x;
    const int wid = tid >> 5;
    const int lane = tid & 31;
    const int g = lane >> 2;              // groupID 0..7 (mma fragment row)
    const int tig = lane & 3;             // thread-in-group 0..3
    const int qt = lane >> 3;             // ldmatrix tile id 0..3
    const int rr = lane & 7;              // ldmatrix row within tile

    const int n0 = blockIdx.x * BN;
    const int m0 = blockIdx.y * BM;
    const int warp_m = (wid >> 1) * 32;   // 0,32,64,96
    const int warp_n = (wid & 1) * 64;    // 0,64
    const int nchunk = K >> 5;

    const float* Ab = A + (size_t)m0 * K;
    const float* Bb = B + (size_t)n0 * K;

    const uint32_t smb = smem_u32(sm);
    // per-lane ldmatrix byte offsets (k=0) within a stage
    // A tiles (per mt): {rows r0..r0+7 | k..k+3}, {rows+8 | k..k+3}, {rows | k+4..7}, {rows+8 | k+4..7}
    uint32_t a_loff[2], b_loff[4];
#pragma unroll
    for (int mt = 0; mt < 2; mt++)
        a_loff[mt] = ((warp_m + mt * 16 + ((qt & 1) << 3) + rr) * LDT + ((qt >> 1) << 2)) * 4;
    // B tile-pairs (per p, covering nt=2p,2p+1): {n..n+7 | k..k+3}, {n..n+7 | k+4..7}, {n+8.. | k..}, {n+8.. | k+4..}
#pragma unroll
    for (int p = 0; p < 4; p++)
        b_loff[p] = (TILE_F + (warp_n + p * 16 + ((qt >> 1) << 3) + rr) * LDT + ((qt & 1) << 2)) * 4;

    float acc[2][8][4];
#pragma unroll
    for (int mt = 0; mt < 2; mt++)
#pragma unroll
        for (int nt = 0; nt < 8; nt++)
#pragma unroll
            for (int q = 0; q < 4; q++) acc[mt][nt][q] = 0.0f;

    // prologue: issue stages 0,1
#pragma unroll
    for (int s = 0; s < 2; s++) {
        float* st = sm + s * STAGE_F;
        load_tile(st, Ab + s * BK, K, tid);
        load_tile(st + TILE_F, Bb + s * BK, K, tid);
        CP_COMMIT();
    }

    for (int c = 0; c < nchunk; c++) {
        CP_WAIT(1);
        __syncthreads();

        // issue chunk c+2 into buffer (c+2)%3 (freed by the barrier above)
        if (c + 2 < nchunk) {
            int s = (c + 2) % NSTAGE;
            float* st = sm + s * STAGE_F;
            load_tile(st, Ab + (c + 2) * BK, K, tid);
            load_tile(st + TILE_F, Bb + (c + 2) * BK, K, tid);
            CP_COMMIT();
        }

        const uint32_t stg = smb + (uint32_t)((c % NSTAGE) * STAGE_F * 4);

#pragma unroll
        for (int ks = 0; ks < 4; ks++) {
            const uint32_t kb = ks * 32;          // 8 floats per k-step
            uint32_t af[2][4], bf[4][4];
            ldsm4(af[0], stg + a_loff[0] + kb);
            ldsm4(af[1], stg + a_loff[1] + kb);
#pragma unroll
            for (int p = 0; p < 4; p++) ldsm4(bf[p], stg + b_loff[p] + kb);
#pragma unroll
            for (int mt = 0; mt < 2; mt++)
#pragma unroll
                for (int nt = 0; nt < 8; nt++)
                    mma_tf32(acc[mt][nt], af[mt][0], af[mt][1], af[mt][2], af[mt][3],
                             bf[nt >> 1][(nt & 1) * 2], bf[nt >> 1][(nt & 1) * 2 + 1]);
        }
    }
    CP_WAIT(0);

    // ---- epilogue ----
#pragma unroll
    for (int mt = 0; mt < 2; mt++) {
        const int row_a = m0 + warp_m + mt * 16 + g;
        const int row_b = row_a + 8;
#pragma unroll
        for (int nt = 0; nt < 8; nt++) {
            const int col = n0 + warp_n + nt * 8 + tig * 2;
            const float b0 = bias[col], b1 = bias[col + 1];
            float v0 = acc[mt][nt][0] + b0;
            float v1 = acc[mt][nt][1] + b1;
            float v2 = acc[mt][nt][2] + b0;
            float v3 = acc[mt][nt][3] + b1;
            if (MODE == EP_RELU) {
                v0 = rna_tf32(fmaxf(v0, 0.0f)); v1 = rna_tf32(fmaxf(v1, 0.0f));
                v2 = rna_tf32(fmaxf(v2, 0.0f)); v3 = rna_tf32(fmaxf(v3, 0.0f));
            } else if (MODE == EP_CLAMP_NOISE) {
                v0 = fminf(fmaxf(v0, 0.0f), 1.0f) + jax_awgn_noise((unsigned)((size_t)row_a * N + col));
                v1 = fminf(fmaxf(v1, 0.0f), 1.0f) + jax_awgn_noise((unsigned)((size_t)row_a * N + col + 1));
                v2 = fminf(fmaxf(v2, 0.0f), 1.0f) + jax_awgn_noise((unsigned)((size_t)row_b * N + col));
                v3 = fminf(fmaxf(v3, 0.0f), 1.0f) + jax_awgn_noise((unsigned)((size_t)row_b * N + col + 1));
                v0 = rna_tf32(v0); v1 = rna_tf32(v1); v2 = rna_tf32(v2); v3 = rna_tf32(v3);
            }
            *(float2*)(C + (size_t)row_a * N + col) = make_float2(v0, v1);
            *(float2*)(C + (size_t)row_b * N + col) = make_float2(v2, v3);
        }
    }
}

// ---------------- host launch ----------------
extern "C" void kernel_launch(void* const* d_in, const int* in_sizes, int n_in,
                              void* d_out, int out_size)
{
    (void)in_sizes; (void)n_in; (void)out_size;
    const float* x   = (const float*)d_in[0];
    const float* ew1 = (const float*)d_in[1];
    const float* eb1 = (const float*)d_in[2];
    const float* ew2 = (const float*)d_in[3];
    const float* eb2 = (const float*)d_in[4];
    const float* dw1 = (const float*)d_in[5];
    const float* db1 = (const float*)d_in[6];
    const float* dw2 = (const float*)d_in[7];
    const float* db2 = (const float*)d_in[8];
    float* out = (float*)d_out;

    float *px, *ph, *pz, *w1, *w2, *w3, *w4;
    cudaGetSymbolAddress((void**)&px, g_x);
    cudaGetSymbolAddress((void**)&ph, g_h);
    cudaGetSymbolAddress((void**)&pz, g_z);
    cudaGetSymbolAddress((void**)&w1, g_wt1);
    cudaGetSymbolAddress((void**)&w2, g_wt2);
    cudaGetSymbolAddress((void**)&w3, g_wt3);
    cudaGetSymbolAddress((void**)&w4, g_wt4);

    // prep: tf32-round x; transpose+round the 4 weights into [N,K] layout
    round_tf32_kernel<<<2048, 256>>>((const float4*)x, (float4*)px, (BATCH * IN_CH) / 4);
    dim3 tb(32, 8);
    transpose_rna_kernel<<<dim3(IN_CH / 32, IN_CH / 32), tb>>>(ew1, w1, IN_CH, IN_CH);
    transpose_rna_kernel<<<dim3(COMP  / 32, IN_CH / 32), tb>>>(ew2, w2, IN_CH, COMP);
    transpose_rna_kernel<<<dim3(IN_CH / 32, COMP  / 32), tb>>>(dw1, w3, COMP, IN_CH);
    transpose_rna_kernel<<<dim3(IN_CH / 32, IN_CH / 32), tb>>>(dw2, w4, IN_CH, IN_CH);

    cudaFuncSetAttribute(gemm_mma<EP_RELU>,        cudaFuncAttributeMaxDynamicSharedMemorySize, SMEM_BYTES);
    cudaFuncSetAttribute(gemm_mma<EP_CLAMP_NOISE>, cudaFuncAttributeMaxDynamicSharedMemorySize, SMEM_BYTES);
    cudaFuncSetAttribute(gemm_mma<EP_PLAIN>,       cudaFuncAttributeMaxDynamicSharedMemorySize, SMEM_BYTES);

    // G1: h = relu(x @ enc_w1 + b)            [16384, 4096], K=4096
    gemm_mma<EP_RELU><<<dim3(IN_CH / BN, BATCH / BM), 256, SMEM_BYTES>>>(px, w1, eb1, ph, BATCH, IN_CH, IN_CH);
    // G2: z = clamp(h @ enc_w2 + b) + awgn    [16384, 512],  K=4096
    gemm_mma<EP_CLAMP_NOISE><<<dim3(COMP / BN, BATCH / BM), 256, SMEM_BYTES>>>(ph, w2, eb2, pz, BATCH, COMP, IN_CH);
    // G3: h = relu(z @ dec_w1 + b)            [16384, 4096], K=512
    gemm_mma<EP_RELU><<<dim3(IN_CH / BN, BATCH / BM), 256, SMEM_BYTES>>>(pz, w3, db1, ph, BATCH, IN_CH, COMP);
    // G4: out = h @ dec_w2 + b                [16384, 4096], K=4096
    gemm_mma<EP_PLAIN><<<dim3(IN_CH / BN, BATCH / BM), 256, SMEM_BYTES>>>(ph, w4, db2, out, BATCH, IN_CH, IN_CH);
}